// round 13
// baseline (speedup 1.0000x reference)
#include <cuda_runtime.h>
#include <cuda_fp16.h>
#include <math_constants.h>
#include <cstdint>

#define B_ 256
#define P_ 196
#define E_ 2048
#define D_ 512
#define A_ 512
#define M_ (B_*P_)   // 50176
#define NTILES 784   // 392 row tiles x 2 col halves

// Scratch
__device__ float  g_att2[B_*A_];
__device__ float  g_attp[2*M_];
__device__ __half g_WhT[A_*E_];
__device__ int    g_ready[B_];
__device__ int    g_claim[B_];
__device__ int    g_tile;
__device__ int    g_nclaim;

// ---------------------------------------------------------------------------
__device__ __forceinline__ uint32_t smem_u32(const void* p) {
    uint32_t a;
    asm("{ .reg .u64 t; cvta.to.shared.u64 t, %1; cvt.u32.u64 %0, t; }"
        : "=r"(a) : "l"(p));
    return a;
}
__device__ __forceinline__ void cp16(uint32_t saddr, const void* gaddr) {
    asm volatile("cp.async.cg.shared.global [%0], [%1], 16;\n"
                 :: "r"(saddr), "l"(gaddr));
}
__device__ __forceinline__ void ldsm4(uint32_t* r, uint32_t addr) {
    asm volatile("ldmatrix.sync.aligned.m8n8.x4.shared.b16 {%0,%1,%2,%3}, [%4];"
                 : "=r"(r[0]), "=r"(r[1]), "=r"(r[2]), "=r"(r[3]) : "r"(addr));
}
#define MMA_F16(d, a, b)                                               \
    asm volatile(                                                      \
        "mma.sync.aligned.m16n8k16.row.col.f32.f16.f16.f32 "           \
        "{%0,%1,%2,%3}, {%4,%5,%6,%7}, {%8,%9}, {%0,%1,%2,%3};\n"      \
        : "+f"((d)[0]), "+f"((d)[1]), "+f"((d)[2]), "+f"((d)[3])       \
        : "r"((a)[0]), "r"((a)[1]), "r"((a)[2]), "r"((a)[3]),          \
          "r"((b)[0]), "r"((b)[1]))

// ---------------------------------------------------------------------------
__global__ void init_flags_kernel() {
    int i = threadIdx.x;
    if (i < B_) { g_ready[i] = 0; g_claim[i] = 0; }
    if (i == 0) { g_tile = 0; g_nclaim = 0; }
}

// ---------------------------------------------------------------------------
// Stage 0: transpose + convert Wenc [E,A] f32 -> g_WhT [A,E] fp16
// ---------------------------------------------------------------------------
__global__ void transpose_kernel(const float* __restrict__ W) {
    __shared__ float tile[32][33];
    const int k0 = blockIdx.x * 32, n0 = blockIdx.y * 32;
    for (int i = threadIdx.y; i < 32; i += 8)
        tile[i][threadIdx.x] = W[(size_t)(k0 + i) * A_ + n0 + threadIdx.x];
    __syncthreads();
    for (int i = threadIdx.y; i < 32; i += 8)
        g_WhT[(size_t)(n0 + i) * E_ + k0 + threadIdx.x] =
            __float2half_rn(tile[threadIdx.x][i]);
}

// ---------------------------------------------------------------------------
// Stage 1: att2[b,a] = decoder_hidden[b,:] @ W_dec[:,a] + b_dec[a]
// ---------------------------------------------------------------------------
__global__ void att2_kernel(const float* __restrict__ dh,
                            const float* __restrict__ Wdec,
                            const float* __restrict__ bdec) {
    __shared__ float sdh[16][D_];
    const int colBase = blockIdx.x * 128;
    const int bBase   = blockIdx.y * 16;
    const int t = threadIdx.x;

    for (int i = t; i < 16 * D_; i += 256) {
        int bb = i / D_, k = i % D_;
        sdh[bb][k] = dh[(bBase + bb) * D_ + k];
    }
    __syncthreads();

    const int col   = colBase + (t & 127);
    const int bhalf = t >> 7;
    float acc[8];
    #pragma unroll
    for (int i = 0; i < 8; i++) acc[i] = 0.0f;

    for (int k = 0; k < D_; k++) {
        float w = Wdec[k * A_ + col];
        #pragma unroll
        for (int i = 0; i < 8; i++)
            acc[i] = fmaf(sdh[bhalf * 8 + i][k], w, acc[i]);
    }
    float bd = bdec[col];
    #pragma unroll
    for (int i = 0; i < 8; i++)
        g_att2[(bBase + bhalf * 8 + i) * A_ + col] = acc[i] + bd;
}

// ---------------------------------------------------------------------------
// Stage 2 (persistent): fp16 GEMM tiles from an atomic queue; when the queue
// drains, the CTA switches to claiming completed batches for softmax+awe.
// GEMM machinery identical to R11 (BM=128, BN=256, BK=64, 16 warps, 32x64).
// ---------------------------------------------------------------------------
#define ASB 144                      // smem row stride in bytes
#define KT (E_/64)                   // 32 stages
#define SM_A0 0
#define SM_A1 18432
#define SM_B0 36864
#define SM_B1 73728
#define SM_TOTAL 110592

__global__ __launch_bounds__(512, 1)
void main_gemm_h(const float* __restrict__ enc,
                 const float* __restrict__ benc,
                 const float* __restrict__ wfull,
                 float* __restrict__ alpha_out,
                 float* __restrict__ awe_out) {
    extern __shared__ __align__(128) char smem[];
    __shared__ int s_tile, s_qn, s_done;
    __shared__ int q[B_];
    const uint32_t sb = smem_u32(smem);
    const int tid  = threadIdx.x;
    const int lane = tid & 31;
    const int warp = tid >> 5;
    const int mw   = warp >> 2;          // 0..3  (m block of 32)
    const int nw   = warp & 3;           // 0..3  (n block of 64)

    const uint32_t aBuf[2] = { sb + SM_A0, sb + SM_A1 };
    const uint32_t bBuf[2] = { sb + SM_B0, sb + SM_B1 };

    // ldmatrix per-thread address offsets (tile-independent)
    const uint32_t aOff = (uint32_t)((mw * 32 + (lane & 15)) * ASB)
                        + (uint32_t)((lane >> 4) * 16);
    const int bRow = nw * 64 + (lane & 7) + ((lane >> 4) & 1) * 8;
    const uint32_t bOff = (uint32_t)(bRow * ASB)
                        + (uint32_t)(((lane >> 3) & 1) * 16);

    // loader coords (tile-independent parts)
    const int ar0 = tid >> 3,        aq0 = tid & 7;
    const int ar1 = 64 + (tid >> 3);
    const uint32_t aSt0 = (uint32_t)(ar0 * ASB + aq0 * 16);
    const uint32_t aSt1 = (uint32_t)(ar1 * ASB + aq0 * 16);
    const int br = tid >> 3, bq = tid & 7;
    const uint32_t bSt = (uint32_t)(br * ASB + bq * 16);

    auto cvt8 = [](const float* p) -> uint4 {
        float4 f0 = *(const float4*)p;
        float4 f1 = *(const float4*)(p + 4);
        __half2 h0 = __floats2half2_rn(f0.x, f0.y);
        __half2 h1 = __floats2half2_rn(f0.z, f0.w);
        __half2 h2 = __floats2half2_rn(f1.x, f1.y);
        __half2 h3 = __floats2half2_rn(f1.z, f1.w);
        uint4 u;
        u.x = *(uint32_t*)&h0; u.y = *(uint32_t*)&h1;
        u.z = *(uint32_t*)&h2; u.w = *(uint32_t*)&h3;
        return u;
    };

    // ================= persistent GEMM tile loop =================
    for (;;) {
        if (tid == 0) s_tile = atomicAdd(&g_tile, 1);
        __syncthreads();                 // broadcast + protects smem reuse
        const int tile = s_tile;
        if (tile >= NTILES) break;
        const int rowBase = (tile >> 1) * 128;
        const int part    = tile & 1;
        const int colBase = part * 256;

        const float* aG0 = enc + (size_t)(rowBase + ar0) * E_ + aq0 * 8;
        const float* aG1 = enc + (size_t)(rowBase + ar1) * E_ + aq0 * 8;
        const __half* bG = g_WhT + (size_t)(colBase + br) * E_ + bq * 8;

        auto cpB = [&](int s, int k0) {
            #pragma unroll
            for (int i = 0; i < 4; i++)
                cp16(bBuf[s] + bSt + (uint32_t)(i * 64 * ASB),
                     bG + k0 + (size_t)(i * 64) * E_);
            asm volatile("cp.async.commit_group;\n" ::: "memory");
        };

        float acc[2][8][4];
        #pragma unroll
        for (int mi = 0; mi < 2; mi++)
            #pragma unroll
            for (int nj = 0; nj < 8; nj++)
                #pragma unroll
                for (int e = 0; e < 4; e++) acc[mi][nj][e] = 0.0f;

        // prologue: stage 0
        *(uint4*)(smem + SM_A0 + aSt0) = cvt8(aG0);
        *(uint4*)(smem + SM_A0 + aSt1) = cvt8(aG1);
        cpB(0, 0);

        for (int t = 0; t < KT; t++) {
            const int s = t & 1;
            asm volatile("cp.async.wait_group 0;\n" ::: "memory");
            __syncthreads();

            uint4 aN0, aN1;
            if (t + 1 < KT) {
                cpB(s ^ 1, (t + 1) * 64);
                aN0 = cvt8(aG0 + (t + 1) * 64);
                aN1 = cvt8(aG1 + (t + 1) * 64);
            }

            const uint32_t aB = aBuf[s], bB = bBuf[s];
            #pragma unroll
            for (int kk = 0; kk < 4; kk++) {
                uint32_t af[2][4];
                ldsm4(af[0], aB + aOff + kk * 32);
                ldsm4(af[1], aB + aOff + 16 * ASB + kk * 32);
                uint32_t bf[8][2];
                #pragma unroll
                for (int p = 0; p < 4; p++) {
                    uint32_t r4[4];
                    ldsm4(r4, bB + bOff + p * 16 * ASB + kk * 32);
                    bf[2*p][0]   = r4[0]; bf[2*p][1]   = r4[1];
                    bf[2*p+1][0] = r4[2]; bf[2*p+1][1] = r4[3];
                }
                #pragma unroll
                for (int mi = 0; mi < 2; mi++)
                    #pragma unroll
                    for (int nj = 0; nj < 8; nj++)
                        MMA_F16(acc[mi][nj], af[mi], bf[nj]);
            }

            if (t + 1 < KT) {
                char* dst = smem + (s ? SM_A0 : SM_A1);
                *(uint4*)(dst + aSt0) = aN0;
                *(uint4*)(dst + aSt1) = aN1;
            }
        }

        // ---- epilogue: relu(att1 + benc + att2) . wfull, per-row sums ----
        __syncthreads();
        float* sa2 = (float*)smem;       // [2][256]
        float* sw  = (float*)smem + 512; // [256]
        float* red = (float*)smem + 768; // [128][5]
        const int b0 = rowBase / P_;
        const int boundary = (b0 + 1) * P_ - rowBase;

        {
            int bb = b0 + (tid >> 8); if (bb > B_ - 1) bb = B_ - 1;
            int c = tid & 255;
            sa2[tid] = benc[colBase + c] + g_att2[bb * A_ + colBase + c];
        }
        if (tid < 256) sw[tid] = wfull[colBase + tid];
        __syncthreads();

        const int c0l = nw * 64 + 2 * (lane & 3);
        #pragma unroll
        for (int mi = 0; mi < 2; mi++) {
            #pragma unroll
            for (int h = 0; h < 2; h++) {
                const int rl = mw * 32 + mi * 16 + h * 8 + (lane >> 2);
                const float* a2p = sa2 + ((rl >= boundary) ? 256 : 0);
                float s = 0.0f;
                #pragma unroll
                for (int nj = 0; nj < 8; nj++) {
                    const int c = c0l + nj * 8;
                    float v0 = acc[mi][nj][h * 2 + 0] + a2p[c];
                    float v1 = acc[mi][nj][h * 2 + 1] + a2p[c + 1];
                    s = fmaf(fmaxf(v0, 0.0f), sw[c], s);
                    s = fmaf(fmaxf(v1, 0.0f), sw[c + 1], s);
                }
                s += __shfl_xor_sync(0xFFFFFFFFu, s, 1);
                s += __shfl_xor_sync(0xFFFFFFFFu, s, 2);
                if ((lane & 3) == 0) red[rl * 5 + nw] = s;
            }
        }
        __syncthreads();
        if (tid < 128) {
            g_attp[part * M_ + rowBase + tid] =
                red[tid * 5 + 0] + red[tid * 5 + 1]
              + red[tid * 5 + 2] + red[tid * 5 + 3];
        }
        __syncthreads();
        if (tid == 0) {
            __threadfence();             // logits visible before counters
            int bLast = (rowBase + 127) / P_; if (bLast > B_ - 1) bLast = B_ - 1;
            for (int b = b0; b <= bLast; b++) atomicAdd(&g_ready[b], 1);
        }
        // loop-top __syncthreads protects red/sa2 vs next prologue stores
    }

    // ================= tail: claim ready batches, softmax + awe =============
    float* sal  = (float*)smem;            // [256] alpha scratch
    float* sred = (float*)(smem + 1024);   // [256] reduction

    for (;;) {
        if (tid == 0) s_qn = 0;
        __syncthreads();
        if (tid < B_) {
            const int b = tid;
            if (*(volatile int*)&g_claim[b] == 0) {
                int first = (P_ * b) >> 7;
                int last  = (P_ * b + P_ - 1) >> 7;
                int expd  = 2 * (last - first + 1);
                if (*(volatile int*)&g_ready[b] == expd) {
                    if (atomicCAS(&g_claim[b], 0, 1) == 0) {
                        q[atomicAdd(&s_qn, 1)] = b;
                        atomicAdd(&g_nclaim, 1);
                    }
                }
            }
        }
        __syncthreads();
        const int n = s_qn;
        if (n == 0) {
            if (tid == 0) s_done = *(volatile int*)&g_nclaim;
            __syncthreads();
            if (s_done >= B_) break;
            __nanosleep(1000);
            continue;
        }
        __threadfence();                   // acquire before reading g_attp

        for (int i = 0; i < n; i++) {
            const int b = q[i];
            // softmax over P_=196
            float v = -CUDART_INF_F;
            if (tid < P_) {
                int r = b * P_ + tid;
                v = g_attp[r] + g_attp[M_ + r];
            }
            if (tid < 256) sred[tid] = v;
            __syncthreads();
            for (int s = 128; s > 0; s >>= 1) {
                if (tid < s) sred[tid] = fmaxf(sred[tid], sred[tid + s]);
                __syncthreads();
            }
            const float m = sred[0];
            __syncthreads();
            float e = (tid < P_) ? expf(v - m) : 0.0f;
            if (tid < 256) sred[tid] = e;
            __syncthreads();
            for (int s = 128; s > 0; s >>= 1) {
                if (tid < s) sred[tid] += sred[tid + s];
                __syncthreads();
            }
            const float inv = 1.0f / sred[0];
            __syncthreads();
            if (tid < P_) {
                float a = e * inv;
                sal[tid] = a;
                alpha_out[b * P_ + tid] = a;
            }
            __syncthreads();

            // awe[b,:]: 512 threads x one float4 column each, MLP-4 p-loop
            const float4* ep = (const float4*)(enc + (size_t)b * P_ * E_) + tid;
            float ax = 0.f, ay = 0.f, az = 0.f, aw = 0.f;
            #pragma unroll 2
            for (int p = 0; p < 196; p += 4) {
                float4 x0 = ep[(size_t)(p + 0) * 512]; float w0 = sal[p + 0];
                float4 x1 = ep[(size_t)(p + 1) * 512]; float w1 = sal[p + 1];
                float4 x2 = ep[(size_t)(p + 2) * 512]; float w2 = sal[p + 2];
                float4 x3 = ep[(size_t)(p + 3) * 512]; float w3 = sal[p + 3];
                ax = fmaf(x0.x, w0, ax); ay = fmaf(x0.y, w0, ay);
                az = fmaf(x0.z, w0, az); aw = fmaf(x0.w, w0, aw);
                ax = fmaf(x1.x, w1, ax); ay = fmaf(x1.y, w1, ay);
                az = fmaf(x1.z, w1, az); aw = fmaf(x1.w, w1, aw);
                ax = fmaf(x2.x, w2, ax); ay = fmaf(x2.y, w2, ay);
                az = fmaf(x2.z, w2, az); aw = fmaf(x2.w, w2, aw);
                ax = fmaf(x3.x, w3, ax); ay = fmaf(x3.y, w3, ay);
                az = fmaf(x3.z, w3, az); aw = fmaf(x3.w, w3, aw);
            }
            float4 r4; r4.x = ax; r4.y = ay; r4.z = az; r4.w = aw;
            *(float4*)(awe_out + (size_t)b * E_ + tid * 4) = r4;
            __syncthreads();
        }
    }
}

// ---------------------------------------------------------------------------
extern "C" void kernel_launch(void* const* d_in, const int* in_sizes, int n_in,
                              void* d_out, int out_size) {
    const float* enc   = (const float*)d_in[0];
    const float* dh    = (const float*)d_in[1];
    const float* Wenc  = (const float*)d_in[2];
    const float* benc  = (const float*)d_in[3];
    const float* Wdec  = (const float*)d_in[4];
    const float* bdec  = (const float*)d_in[5];
    const float* wfull = (const float*)d_in[6];
    // d_in[7] = b_full: softmax-invariant, dropped.

    float* awe   = (float*)d_out;
    float* alpha = (float*)d_out + (size_t)B_ * E_;

    static int nsm = 0;
    if (!nsm) {
        cudaDeviceProp prop;
        cudaGetDeviceProperties(&prop, 0);
        nsm = prop.multiProcessorCount;
        cudaFuncSetAttribute(main_gemm_h,
                             cudaFuncAttributeMaxDynamicSharedMemorySize,
                             SM_TOTAL);
    }

    init_flags_kernel<<<1, 512>>>();
    transpose_kernel<<<dim3(E_ / 32, A_ / 32), dim3(32, 8)>>>(Wenc);
    att2_kernel<<<dim3(A_ / 128, B_ / 16), 256>>>(dh, Wdec, bdec);
    main_gemm_h<<<nsm, 512, SM_TOTAL>>>(enc, benc, wfull, alpha, awe);
}

// round 14
// speedup vs baseline: 7.2487x; 7.2487x over previous
#include <cuda_runtime.h>
#include <cuda_fp16.h>
#include <math_constants.h>
#include <cstdint>

#define B_ 256
#define P_ 196
#define E_ 2048
#define D_ 512
#define A_ 512
#define M_ (B_*P_)   // 50176

// Scratch: att2 [B,A], partial logits [2][M], fp16-transposed Wenc [A,E]
__device__ float  g_att2[B_*A_];
__device__ float  g_attp[2*M_];
__device__ __half g_WhT[A_*E_];

// ---------------------------------------------------------------------------
__device__ __forceinline__ uint32_t smem_u32(const void* p) {
    uint32_t a;
    asm("{ .reg .u64 t; cvta.to.shared.u64 t, %1; cvt.u32.u64 %0, t; }"
        : "=r"(a) : "l"(p));
    return a;
}
__device__ __forceinline__ void cp16(uint32_t saddr, const void* gaddr) {
    asm volatile("cp.async.cg.shared.global [%0], [%1], 16;\n"
                 :: "r"(saddr), "l"(gaddr));
}
__device__ __forceinline__ void ldsm4(uint32_t* r, uint32_t addr) {
    asm volatile("ldmatrix.sync.aligned.m8n8.x4.shared.b16 {%0,%1,%2,%3}, [%4];"
                 : "=r"(r[0]), "=r"(r[1]), "=r"(r[2]), "=r"(r[3]) : "r"(addr));
}
#define MMA_F16(d, a, b)                                               \
    asm volatile(                                                      \
        "mma.sync.aligned.m16n8k16.row.col.f32.f16.f16.f32 "           \
        "{%0,%1,%2,%3}, {%4,%5,%6,%7}, {%8,%9}, {%0,%1,%2,%3};\n"      \
        : "+f"((d)[0]), "+f"((d)[1]), "+f"((d)[2]), "+f"((d)[3])       \
        : "r"((a)[0]), "r"((a)[1]), "r"((a)[2]), "r"((a)[3]),          \
          "r"((b)[0]), "r"((b)[1]))

// ---------------------------------------------------------------------------
// Stage 0: transpose + convert Wenc [E,A] f32 -> g_WhT [A,E] fp16
// ---------------------------------------------------------------------------
__global__ void transpose_kernel(const float* __restrict__ W) {
    __shared__ float tile[32][33];
    const int k0 = blockIdx.x * 32, n0 = blockIdx.y * 32;
    for (int i = threadIdx.y; i < 32; i += 8)
        tile[i][threadIdx.x] = W[(size_t)(k0 + i) * A_ + n0 + threadIdx.x];
    __syncthreads();
    for (int i = threadIdx.y; i < 32; i += 8)
        g_WhT[(size_t)(n0 + i) * E_ + k0 + threadIdx.x] =
            __float2half_rn(tile[threadIdx.x][i]);
}

// ---------------------------------------------------------------------------
// Stage 1: att2[b,a] = decoder_hidden[b,:] @ W_dec[:,a] + b_dec[a]
// ---------------------------------------------------------------------------
__global__ void att2_kernel(const float* __restrict__ dh,
                            const float* __restrict__ Wdec,
                            const float* __restrict__ bdec) {
    __shared__ float sdh[16][D_];
    const int colBase = blockIdx.x * 128;
    const int bBase   = blockIdx.y * 16;
    const int t = threadIdx.x;

    for (int i = t; i < 16 * D_; i += 256) {
        int bb = i / D_, k = i % D_;
        sdh[bb][k] = dh[(bBase + bb) * D_ + k];
    }
    __syncthreads();

    const int col   = colBase + (t & 127);
    const int bhalf = t >> 7;
    float acc[8];
    #pragma unroll
    for (int i = 0; i < 8; i++) acc[i] = 0.0f;

    for (int k = 0; k < D_; k++) {
        float w = Wdec[k * A_ + col];
        #pragma unroll
        for (int i = 0; i < 8; i++)
            acc[i] = fmaf(sdh[bhalf * 8 + i][k], w, acc[i]);
    }
    float bd = bdec[col];
    #pragma unroll
    for (int i = 0; i < 8; i++)
        g_att2[(bBase + bhalf * 8 + i) * A_ + col] = acc[i] + bd;
}

// ---------------------------------------------------------------------------
// Stage 2: fp16 mma.sync GEMM + fused epilogue (R11 machinery, unchanged).
//   BM=128, BN=256, BK=64, 512 threads (16 warps, warp tile 32x64).
// ---------------------------------------------------------------------------
#define ASB 144                      // smem row stride in bytes
#define KT (E_/64)                   // 32 stages
#define SM_A0 0                      // A buf: 128*144 = 18432 B
#define SM_A1 18432
#define SM_B0 36864                  // B buf: 256*144 = 36864 B
#define SM_B1 73728
#define SM_TOTAL 110592

__global__ __launch_bounds__(512, 1)
void main_gemm_h(const float* __restrict__ enc,
                 const float* __restrict__ benc,
                 const float* __restrict__ wfull) {
    extern __shared__ __align__(128) char smem[];
    const uint32_t sb = smem_u32(smem);
    const int tid  = threadIdx.x;
    const int lane = tid & 31;
    const int warp = tid >> 5;
    const int mw   = warp >> 2;          // 0..3  (m block of 32)
    const int nw   = warp & 3;           // 0..3  (n block of 64)
    const int rowBase = blockIdx.x * 128;
    const int colBase = blockIdx.y * 256;
    const int part    = blockIdx.y;

    const uint32_t aBuf[2] = { sb + SM_A0, sb + SM_A1 };
    const uint32_t bBuf[2] = { sb + SM_B0, sb + SM_B1 };

    // ldmatrix per-thread address offsets (R7 formulas, stride 144B)
    const uint32_t aOff = (uint32_t)((mw * 32 + (lane & 15)) * ASB)
                        + (uint32_t)((lane >> 4) * 16);
    const int bRow = nw * 64 + (lane & 7) + ((lane >> 4) & 1) * 8;
    const uint32_t bOff = (uint32_t)(bRow * ASB)
                        + (uint32_t)(((lane >> 3) & 1) * 16);

    // A loader: 128 rows x 8 chunks(16B fp16 = 8 floats) = 1024 / 512 thr = 2
    const int ar0 = tid >> 3,        aq0 = tid & 7;
    const int ar1 = 64 + (tid >> 3), aq1 = tid & 7;
    const float* aG0 = enc + (size_t)(rowBase + ar0) * E_ + aq0 * 8;
    const float* aG1 = enc + (size_t)(rowBase + ar1) * E_ + aq1 * 8;
    const uint32_t aSt0 = (uint32_t)(ar0 * ASB + aq0 * 16);
    const uint32_t aSt1 = (uint32_t)(ar1 * ASB + aq1 * 16);

    // B loader: 256 rows x 8 chunks = 2048 / 512 thr = 4 each
    const int br = tid >> 3, bq = tid & 7;
    const __half* bG = g_WhT + (size_t)(colBase + br) * E_ + bq * 8;
    const uint32_t bSt = (uint32_t)(br * ASB + bq * 16);

    auto cvt8 = [](const float* p) -> uint4 {
        float4 f0 = *(const float4*)p;
        float4 f1 = *(const float4*)(p + 4);
        __half2 h0 = __floats2half2_rn(f0.x, f0.y);
        __half2 h1 = __floats2half2_rn(f0.z, f0.w);
        __half2 h2 = __floats2half2_rn(f1.x, f1.y);
        __half2 h3 = __floats2half2_rn(f1.z, f1.w);
        uint4 u;
        u.x = *(uint32_t*)&h0; u.y = *(uint32_t*)&h1;
        u.z = *(uint32_t*)&h2; u.w = *(uint32_t*)&h3;
        return u;
    };
    auto cpB = [&](int s, int k0) {
        #pragma unroll
        for (int i = 0; i < 4; i++)   // 4 x 64 rows
            cp16(bBuf[s] + bSt + (uint32_t)(i * 64 * ASB),
                 bG + k0 + (size_t)(i * 64) * E_);
        asm volatile("cp.async.commit_group;\n" ::: "memory");
    };

    float acc[2][8][4];
    #pragma unroll
    for (int mi = 0; mi < 2; mi++)
        #pragma unroll
        for (int nj = 0; nj < 8; nj++)
            #pragma unroll
            for (int e = 0; e < 4; e++) acc[mi][nj][e] = 0.0f;

    // prologue: stage 0
    {
        *(uint4*)(smem + SM_A0 + aSt0) = cvt8(aG0);
        *(uint4*)(smem + SM_A0 + aSt1) = cvt8(aG1);
        cpB(0, 0);
    }

    for (int t = 0; t < KT; t++) {
        const int s = t & 1;
        asm volatile("cp.async.wait_group 0;\n" ::: "memory");
        __syncthreads();

        uint4 aN0, aN1;
        if (t + 1 < KT) {
            cpB(s ^ 1, (t + 1) * 64);
            aN0 = cvt8(aG0 + (t + 1) * 64);
            aN1 = cvt8(aG1 + (t + 1) * 64);
        }

        const uint32_t aB = aBuf[s], bB = bBuf[s];
        #pragma unroll
        for (int kk = 0; kk < 4; kk++) {
            uint32_t af[2][4];
            ldsm4(af[0], aB + aOff + kk * 32);
            ldsm4(af[1], aB + aOff + 16 * ASB + kk * 32);
            uint32_t bf[8][2];
            #pragma unroll
            for (int p = 0; p < 4; p++) {
                uint32_t r4[4];
                ldsm4(r4, bB + bOff + p * 16 * ASB + kk * 32);
                bf[2*p][0]   = r4[0]; bf[2*p][1]   = r4[1];
                bf[2*p+1][0] = r4[2]; bf[2*p+1][1] = r4[3];
            }
            #pragma unroll
            for (int mi = 0; mi < 2; mi++)
                #pragma unroll
                for (int nj = 0; nj < 8; nj++)
                    MMA_F16(acc[mi][nj], af[mi], bf[nj]);
        }

        if (t + 1 < KT) {
            char* dst = smem + (s ? SM_A0 : SM_A1);
            *(uint4*)(dst + aSt0) = aN0;
            *(uint4*)(dst + aSt1) = aN1;
        }
    }

    // ---- fused epilogue: relu(att1 + benc + att2) . wfull, per-row sums ----
    __syncthreads();                 // reuse smem
    float* sa2 = (float*)smem;       // [2][256]: benc + att2 for 2 local batches
    float* sw  = (float*)smem + 512; // [256]
    float* red = (float*)smem + 768; // [128][5]
    const int b0 = rowBase / P_;
    const int boundary = (b0 + 1) * P_ - rowBase;   // local row where batch++

    {
        int bb = b0 + (tid >> 8); if (bb > B_ - 1) bb = B_ - 1;
        int c = tid & 255;
        sa2[tid] = benc[colBase + c] + g_att2[bb * A_ + colBase + c];
    }
    if (tid < 256) sw[tid] = wfull[colBase + tid];
    __syncthreads();

    const int c0l = nw * 64 + 2 * (lane & 3);
    #pragma unroll
    for (int mi = 0; mi < 2; mi++) {
        #pragma unroll
        for (int h = 0; h < 2; h++) {
            const int rl = mw * 32 + mi * 16 + h * 8 + (lane >> 2);
            const float* a2p = sa2 + ((rl >= boundary) ? 256 : 0);
            float s = 0.0f;
            #pragma unroll
            for (int nj = 0; nj < 8; nj++) {
                const int c = c0l + nj * 8;
                float v0 = acc[mi][nj][h * 2 + 0] + a2p[c];
                float v1 = acc[mi][nj][h * 2 + 1] + a2p[c + 1];
                s = fmaf(fmaxf(v0, 0.0f), sw[c], s);
                s = fmaf(fmaxf(v1, 0.0f), sw[c + 1], s);
            }
            s += __shfl_xor_sync(0xFFFFFFFFu, s, 1);
            s += __shfl_xor_sync(0xFFFFFFFFu, s, 2);
            if ((lane & 3) == 0) red[rl * 5 + nw] = s;
        }
    }
    __syncthreads();
    if (tid < 128) {
        g_attp[part * M_ + rowBase + tid] =
            red[tid * 5 + 0] + red[tid * 5 + 1]
          + red[tid * 5 + 2] + red[tid * 5 + 3];
    }
}

// ---------------------------------------------------------------------------
// Stage 3 (fused softmax + awe): grid (E/256, B), 256 threads.
//   Each CTA recomputes the softmax of its batch from g_attp (cheap,
//   L2-resident), then accumulates its 256-column slice of awe with MLP-4
//   batched loads. blockIdx.x==0 CTAs also write alpha.
// ---------------------------------------------------------------------------
__global__ void awe_kernel(const float* __restrict__ enc,
                           float* __restrict__ alpha_out,
                           float* __restrict__ awe_out) {
    __shared__ float sred[256];
    __shared__ float sa[P_];
    const int b = blockIdx.y;
    const int t = threadIdx.x;

    // softmax over P_=196 for batch b
    float v = -CUDART_INF_F;
    if (t < P_) {
        int r = b * P_ + t;
        v = g_attp[r] + g_attp[M_ + r];
    }
    sred[t] = v;
    __syncthreads();
    for (int s = 128; s > 0; s >>= 1) {
        if (t < s) sred[t] = fmaxf(sred[t], sred[t + s]);
        __syncthreads();
    }
    const float m = sred[0];
    __syncthreads();
    float e = (t < P_) ? expf(v - m) : 0.0f;
    sred[t] = e;
    __syncthreads();
    for (int s = 128; s > 0; s >>= 1) {
        if (t < s) sred[t] += sred[t + s];
        __syncthreads();
    }
    const float inv = 1.0f / sred[0];
    __syncthreads();
    if (t < P_) {
        float a = e * inv;
        sa[t] = a;
        if (blockIdx.x == 0) alpha_out[b * P_ + t] = a;
    }
    __syncthreads();

    // awe slice: MLP-4 p-loop (196 = 49 * 4)
    const int col = blockIdx.x * 256 + t;
    const float* base = enc + (size_t)b * P_ * E_ + col;
    float acc = 0.0f;
    #pragma unroll 2
    for (int p = 0; p < P_; p += 4) {
        float x0 = base[(size_t)(p + 0) * E_];
        float x1 = base[(size_t)(p + 1) * E_];
        float x2 = base[(size_t)(p + 2) * E_];
        float x3 = base[(size_t)(p + 3) * E_];
        acc = fmaf(x0, sa[p + 0], acc);
        acc = fmaf(x1, sa[p + 1], acc);
        acc = fmaf(x2, sa[p + 2], acc);
        acc = fmaf(x3, sa[p + 3], acc);
    }
    awe_out[(size_t)b * E_ + col] = acc;
}

// ---------------------------------------------------------------------------
extern "C" void kernel_launch(void* const* d_in, const int* in_sizes, int n_in,
                              void* d_out, int out_size) {
    const float* enc   = (const float*)d_in[0];
    const float* dh    = (const float*)d_in[1];
    const float* Wenc  = (const float*)d_in[2];
    const float* benc  = (const float*)d_in[3];
    const float* Wdec  = (const float*)d_in[4];
    const float* bdec  = (const float*)d_in[5];
    const float* wfull = (const float*)d_in[6];
    // d_in[7] = b_full: softmax-invariant, dropped.

    float* awe   = (float*)d_out;
    float* alpha = (float*)d_out + (size_t)B_ * E_;

    static int smem_set = 0;
    if (!smem_set) {
        cudaFuncSetAttribute(main_gemm_h,
                             cudaFuncAttributeMaxDynamicSharedMemorySize,
                             SM_TOTAL);
        smem_set = 1;
    }

    transpose_kernel<<<dim3(E_ / 32, A_ / 32), dim3(32, 8)>>>(Wenc);
    att2_kernel<<<dim3(A_ / 128, B_ / 16), 256>>>(dh, Wdec, bdec);
    main_gemm_h<<<dim3(M_ / 128, 2), 512, SM_TOTAL>>>(enc, benc, wfull);
    awe_kernel<<<dim3(E_ / 256, B_), 256>>>(enc, alpha, awe);
}

// round 15
// speedup vs baseline: 7.6097x; 1.0498x over previous
#include <cuda_runtime.h>
#include <cuda_fp16.h>
#include <math_constants.h>
#include <cstdint>

#define B_ 256
#define P_ 196
#define E_ 2048
#define D_ 512
#define A_ 512
#define M_ (B_*P_)   // 50176

// Scratch: att2 [B,A], partial logits [2][M], fp16-transposed Wenc [A,E]
__device__ float  g_att2[B_*A_];
__device__ float  g_attp[2*M_];
__device__ __half g_WhT[A_*E_];

// ---------------------------------------------------------------------------
__device__ __forceinline__ uint32_t smem_u32(const void* p) {
    uint32_t a;
    asm("{ .reg .u64 t; cvta.to.shared.u64 t, %1; cvt.u32.u64 %0, t; }"
        : "=r"(a) : "l"(p));
    return a;
}
__device__ __forceinline__ void cp16(uint32_t saddr, const void* gaddr) {
    asm volatile("cp.async.cg.shared.global [%0], [%1], 16;\n"
                 :: "r"(saddr), "l"(gaddr));
}
__device__ __forceinline__ void ldsm4(uint32_t* r, uint32_t addr) {
    asm volatile("ldmatrix.sync.aligned.m8n8.x4.shared.b16 {%0,%1,%2,%3}, [%4];"
                 : "=r"(r[0]), "=r"(r[1]), "=r"(r[2]), "=r"(r[3]) : "r"(addr));
}
#define MMA_F16(d, a, b)                                               \
    asm volatile(                                                      \
        "mma.sync.aligned.m16n8k16.row.col.f32.f16.f16.f32 "           \
        "{%0,%1,%2,%3}, {%4,%5,%6,%7}, {%8,%9}, {%0,%1,%2,%3};\n"      \
        : "+f"((d)[0]), "+f"((d)[1]), "+f"((d)[2]), "+f"((d)[3])       \
        : "r"((a)[0]), "r"((a)[1]), "r"((a)[2]), "r"((a)[3]),          \
          "r"((b)[0]), "r"((b)[1]))

// ---------------------------------------------------------------------------
// Stage 0: transpose + convert Wenc [E,A] f32 -> g_WhT [A,E] fp16
// ---------------------------------------------------------------------------
__global__ void transpose_kernel(const float* __restrict__ W) {
    __shared__ float tile[32][33];
    const int k0 = blockIdx.x * 32, n0 = blockIdx.y * 32;
    for (int i = threadIdx.y; i < 32; i += 8)
        tile[i][threadIdx.x] = W[(size_t)(k0 + i) * A_ + n0 + threadIdx.x];
    __syncthreads();
    for (int i = threadIdx.y; i < 32; i += 8)
        g_WhT[(size_t)(n0 + i) * E_ + k0 + threadIdx.x] =
            __float2half_rn(tile[threadIdx.x][i]);
}

// ---------------------------------------------------------------------------
// Stage 1: att2[b,a] = decoder_hidden[b,:] @ W_dec[:,a] + b_dec[a]
// ---------------------------------------------------------------------------
__global__ void att2_kernel(const float* __restrict__ dh,
                            const float* __restrict__ Wdec,
                            const float* __restrict__ bdec) {
    __shared__ float sdh[16][D_];
    const int colBase = blockIdx.x * 128;
    const int bBase   = blockIdx.y * 16;
    const int t = threadIdx.x;

    for (int i = t; i < 16 * D_; i += 256) {
        int bb = i / D_, k = i % D_;
        sdh[bb][k] = dh[(bBase + bb) * D_ + k];
    }
    __syncthreads();

    const int col   = colBase + (t & 127);
    const int bhalf = t >> 7;
    float acc[8];
    #pragma unroll
    for (int i = 0; i < 8; i++) acc[i] = 0.0f;

    for (int k = 0; k < D_; k++) {
        float w = Wdec[k * A_ + col];
        #pragma unroll
        for (int i = 0; i < 8; i++)
            acc[i] = fmaf(sdh[bhalf * 8 + i][k], w, acc[i]);
    }
    float bd = bdec[col];
    #pragma unroll
    for (int i = 0; i < 8; i++)
        g_att2[(bBase + bhalf * 8 + i) * A_ + col] = acc[i] + bd;
}

// ---------------------------------------------------------------------------
// Stage 2: fp16 mma.sync GEMM + fused epilogue (R11/R14 machinery, unchanged
// except rowTileOff parameter for the two-half split).
//   BM=128, BN=256, BK=64, 512 threads (16 warps, warp tile 32x64).
// ---------------------------------------------------------------------------
#define ASB 144                      // smem row stride in bytes
#define KT (E_/64)                   // 32 stages
#define SM_A0 0                      // A buf: 128*144 = 18432 B
#define SM_A1 18432
#define SM_B0 36864                  // B buf: 256*144 = 36864 B
#define SM_B1 73728
#define SM_TOTAL 110592

__global__ __launch_bounds__(512, 1)
void main_gemm_h(const float* __restrict__ enc,
                 const float* __restrict__ benc,
                 const float* __restrict__ wfull,
                 int rowTileOff) {
    extern __shared__ __align__(128) char smem[];
    const uint32_t sb = smem_u32(smem);
    const int tid  = threadIdx.x;
    const int lane = tid & 31;
    const int warp = tid >> 5;
    const int mw   = warp >> 2;          // 0..3  (m block of 32)
    const int nw   = warp & 3;           // 0..3  (n block of 64)
    const int rowBase = (blockIdx.x + rowTileOff) * 128;
    const int colBase = blockIdx.y * 256;
    const int part    = blockIdx.y;

    const uint32_t aBuf[2] = { sb + SM_A0, sb + SM_A1 };
    const uint32_t bBuf[2] = { sb + SM_B0, sb + SM_B1 };

    // ldmatrix per-thread address offsets (R7 formulas, stride 144B)
    const uint32_t aOff = (uint32_t)((mw * 32 + (lane & 15)) * ASB)
                        + (uint32_t)((lane >> 4) * 16);
    const int bRow = nw * 64 + (lane & 7) + ((lane >> 4) & 1) * 8;
    const uint32_t bOff = (uint32_t)(bRow * ASB)
                        + (uint32_t)(((lane >> 3) & 1) * 16);

    // A loader: 128 rows x 8 chunks(16B fp16 = 8 floats) = 1024 / 512 thr = 2
    const int ar0 = tid >> 3,        aq0 = tid & 7;
    const int ar1 = 64 + (tid >> 3), aq1 = tid & 7;
    const float* aG0 = enc + (size_t)(rowBase + ar0) * E_ + aq0 * 8;
    const float* aG1 = enc + (size_t)(rowBase + ar1) * E_ + aq1 * 8;
    const uint32_t aSt0 = (uint32_t)(ar0 * ASB + aq0 * 16);
    const uint32_t aSt1 = (uint32_t)(ar1 * ASB + aq1 * 16);

    // B loader: 256 rows x 8 chunks = 2048 / 512 thr = 4 each
    const int br = tid >> 3, bq = tid & 7;
    const __half* bG = g_WhT + (size_t)(colBase + br) * E_ + bq * 8;
    const uint32_t bSt = (uint32_t)(br * ASB + bq * 16);

    auto cvt8 = [](const float* p) -> uint4 {
        float4 f0 = *(const float4*)p;
        float4 f1 = *(const float4*)(p + 4);
        __half2 h0 = __floats2half2_rn(f0.x, f0.y);
        __half2 h1 = __floats2half2_rn(f0.z, f0.w);
        __half2 h2 = __floats2half2_rn(f1.x, f1.y);
        __half2 h3 = __floats2half2_rn(f1.z, f1.w);
        uint4 u;
        u.x = *(uint32_t*)&h0; u.y = *(uint32_t*)&h1;
        u.z = *(uint32_t*)&h2; u.w = *(uint32_t*)&h3;
        return u;
    };
    auto cpB = [&](int s, int k0) {
        #pragma unroll
        for (int i = 0; i < 4; i++)   // 4 x 64 rows
            cp16(bBuf[s] + bSt + (uint32_t)(i * 64 * ASB),
                 bG + k0 + (size_t)(i * 64) * E_);
        asm volatile("cp.async.commit_group;\n" ::: "memory");
    };

    float acc[2][8][4];
    #pragma unroll
    for (int mi = 0; mi < 2; mi++)
        #pragma unroll
        for (int nj = 0; nj < 8; nj++)
            #pragma unroll
            for (int e = 0; e < 4; e++) acc[mi][nj][e] = 0.0f;

    // prologue: stage 0
    {
        *(uint4*)(smem + SM_A0 + aSt0) = cvt8(aG0);
        *(uint4*)(smem + SM_A0 + aSt1) = cvt8(aG1);
        cpB(0, 0);
    }

    for (int t = 0; t < KT; t++) {
        const int s = t & 1;
        asm volatile("cp.async.wait_group 0;\n" ::: "memory");
        __syncthreads();

        uint4 aN0, aN1;
        if (t + 1 < KT) {
            cpB(s ^ 1, (t + 1) * 64);
            aN0 = cvt8(aG0 + (t + 1) * 64);
            aN1 = cvt8(aG1 + (t + 1) * 64);
        }

        const uint32_t aB = aBuf[s], bB = bBuf[s];
        #pragma unroll
        for (int kk = 0; kk < 4; kk++) {
            uint32_t af[2][4];
            ldsm4(af[0], aB + aOff + kk * 32);
            ldsm4(af[1], aB + aOff + 16 * ASB + kk * 32);
            uint32_t bf[8][2];
            #pragma unroll
            for (int p = 0; p < 4; p++) {
                uint32_t r4[4];
                ldsm4(r4, bB + bOff + p * 16 * ASB + kk * 32);
                bf[2*p][0]   = r4[0]; bf[2*p][1]   = r4[1];
                bf[2*p+1][0] = r4[2]; bf[2*p+1][1] = r4[3];
            }
            #pragma unroll
            for (int mi = 0; mi < 2; mi++)
                #pragma unroll
                for (int nj = 0; nj < 8; nj++)
                    MMA_F16(acc[mi][nj], af[mi], bf[nj]);
        }

        if (t + 1 < KT) {
            char* dst = smem + (s ? SM_A0 : SM_A1);
            *(uint4*)(dst + aSt0) = aN0;
            *(uint4*)(dst + aSt1) = aN1;
        }
    }

    // ---- fused epilogue: relu(att1 + benc + att2) . wfull, per-row sums ----
    __syncthreads();                 // reuse smem
    float* sa2 = (float*)smem;       // [2][256]: benc + att2 for 2 local batches
    float* sw  = (float*)smem + 512; // [256]
    float* red = (float*)smem + 768; // [128][5]
    const int b0 = rowBase / P_;
    const int boundary = (b0 + 1) * P_ - rowBase;   // local row where batch++

    {
        int bb = b0 + (tid >> 8); if (bb > B_ - 1) bb = B_ - 1;
        int c = tid & 255;
        sa2[tid] = benc[colBase + c] + g_att2[bb * A_ + colBase + c];
    }
    if (tid < 256) sw[tid] = wfull[colBase + tid];
    __syncthreads();

    const int c0l = nw * 64 + 2 * (lane & 3);
    #pragma unroll
    for (int mi = 0; mi < 2; mi++) {
        #pragma unroll
        for (int h = 0; h < 2; h++) {
            const int rl = mw * 32 + mi * 16 + h * 8 + (lane >> 2);
            const float* a2p = sa2 + ((rl >= boundary) ? 256 : 0);
            float s = 0.0f;
            #pragma unroll
            for (int nj = 0; nj < 8; nj++) {
                const int c = c0l + nj * 8;
                float v0 = acc[mi][nj][h * 2 + 0] + a2p[c];
                float v1 = acc[mi][nj][h * 2 + 1] + a2p[c + 1];
                s = fmaf(fmaxf(v0, 0.0f), sw[c], s);
                s = fmaf(fmaxf(v1, 0.0f), sw[c + 1], s);
            }
            s += __shfl_xor_sync(0xFFFFFFFFu, s, 1);
            s += __shfl_xor_sync(0xFFFFFFFFu, s, 2);
            if ((lane & 3) == 0) red[rl * 5 + nw] = s;
        }
    }
    __syncthreads();
    if (tid < 128) {
        g_attp[part * M_ + rowBase + tid] =
            red[tid * 5 + 0] + red[tid * 5 + 1]
          + red[tid * 5 + 2] + red[tid * 5 + 3];
    }
}

// ---------------------------------------------------------------------------
// Stage 3 (fused softmax + awe, R14 body + batch offset): grid (E/256, 128).
// ---------------------------------------------------------------------------
__global__ void awe_kernel(const float* __restrict__ enc,
                           float* __restrict__ alpha_out,
                           float* __restrict__ awe_out,
                           int bOff) {
    __shared__ float sred[256];
    __shared__ float sa[P_];
    const int b = blockIdx.y + bOff;
    const int t = threadIdx.x;

    // softmax over P_=196 for batch b
    float v = -CUDART_INF_F;
    if (t < P_) {
        int r = b * P_ + t;
        v = g_attp[r] + g_attp[M_ + r];
    }
    sred[t] = v;
    __syncthreads();
    for (int s = 128; s > 0; s >>= 1) {
        if (t < s) sred[t] = fmaxf(sred[t], sred[t + s]);
        __syncthreads();
    }
    const float m = sred[0];
    __syncthreads();
    float e = (t < P_) ? expf(v - m) : 0.0f;
    sred[t] = e;
    __syncthreads();
    for (int s = 128; s > 0; s >>= 1) {
        if (t < s) sred[t] += sred[t + s];
        __syncthreads();
    }
    const float inv = 1.0f / sred[0];
    __syncthreads();
    if (t < P_) {
        float a = e * inv;
        sa[t] = a;
        if (blockIdx.x == 0) alpha_out[b * P_ + t] = a;
    }
    __syncthreads();

    // awe slice: MLP-4 p-loop (196 = 49 * 4)
    const int col = blockIdx.x * 256 + t;
    const float* base = enc + (size_t)b * P_ * E_ + col;
    float acc = 0.0f;
    #pragma unroll 2
    for (int p = 0; p < P_; p += 4) {
        float x0 = base[(size_t)(p + 0) * E_];
        float x1 = base[(size_t)(p + 1) * E_];
        float x2 = base[(size_t)(p + 2) * E_];
        float x3 = base[(size_t)(p + 3) * E_];
        acc = fmaf(x0, sa[p + 0], acc);
        acc = fmaf(x1, sa[p + 1], acc);
        acc = fmaf(x2, sa[p + 2], acc);
        acc = fmaf(x3, sa[p + 3], acc);
    }
    awe_out[(size_t)b * E_ + col] = acc;
}

// ---------------------------------------------------------------------------
extern "C" void kernel_launch(void* const* d_in, const int* in_sizes, int n_in,
                              void* d_out, int out_size) {
    const float* enc   = (const float*)d_in[0];
    const float* dh    = (const float*)d_in[1];
    const float* Wenc  = (const float*)d_in[2];
    const float* benc  = (const float*)d_in[3];
    const float* Wdec  = (const float*)d_in[4];
    const float* bdec  = (const float*)d_in[5];
    const float* wfull = (const float*)d_in[6];
    // d_in[7] = b_full: softmax-invariant, dropped.

    float* awe   = (float*)d_out;
    float* alpha = (float*)d_out + (size_t)B_ * E_;

    static cudaStream_t s2 = nullptr;
    static cudaEvent_t evFork = nullptr, evJoin = nullptr;
    if (!s2) {
        cudaFuncSetAttribute(main_gemm_h,
                             cudaFuncAttributeMaxDynamicSharedMemorySize,
                             SM_TOTAL);
        cudaStreamCreateWithFlags(&s2, cudaStreamNonBlocking);
        cudaEventCreateWithFlags(&evFork, cudaEventDisableTiming);
        cudaEventCreateWithFlags(&evJoin, cudaEventDisableTiming);
    }

    transpose_kernel<<<dim3(E_ / 32, A_ / 32), dim3(32, 8)>>>(Wenc);
    att2_kernel<<<dim3(A_ / 128, B_ / 16), 256>>>(dh, Wdec, bdec);

    // GEMM half A: row tiles 0..195  (= batches 0..127 exactly)
    main_gemm_h<<<dim3(196, 2), 512, SM_TOTAL>>>(enc, benc, wfull, 0);
    cudaEventRecord(evFork, 0);
    cudaStreamWaitEvent(s2, evFork, 0);

    // GEMM half B on main stream; awe for batches 0..127 on side stream
    // (awe CTAs fill GEMM_B's wave-quantization holes).
    main_gemm_h<<<dim3(196, 2), 512, SM_TOTAL>>>(enc, benc, wfull, 196);
    awe_kernel<<<dim3(E_ / 256, 128), 256, 0, s2>>>(enc, alpha, awe, 0);

    // awe for batches 128..255 on main stream after GEMM_B; then join.
    awe_kernel<<<dim3(E_ / 256, 128), 256>>>(enc, alpha, awe, 128);
    cudaEventRecord(evJoin, s2);
    cudaStreamWaitEvent(0, evJoin, 0);
}

// round 16
// speedup vs baseline: 7.6828x; 1.0096x over previous
#include <cuda_runtime.h>
#include <cuda_fp16.h>
#include <math_constants.h>
#include <cstdint>

#define B_ 256
#define P_ 196
#define E_ 2048
#define D_ 512
#define A_ 512
#define M_ (B_*P_)   // 50176

// Scratch: att2 [B,A], partial logits [2][M], fp16-transposed Wenc [A,E]
__device__ float  g_att2[B_*A_];
__device__ float  g_attp[2*M_];
__device__ __half g_WhT[A_*E_];

// ---------------------------------------------------------------------------
__device__ __forceinline__ uint32_t smem_u32(const void* p) {
    uint32_t a;
    asm("{ .reg .u64 t; cvta.to.shared.u64 t, %1; cvt.u32.u64 %0, t; }"
        : "=r"(a) : "l"(p));
    return a;
}
__device__ __forceinline__ void cp16(uint32_t saddr, const void* gaddr) {
    asm volatile("cp.async.cg.shared.global [%0], [%1], 16;\n"
                 :: "r"(saddr), "l"(gaddr));
}
__device__ __forceinline__ void ldsm4(uint32_t* r, uint32_t addr) {
    asm volatile("ldmatrix.sync.aligned.m8n8.x4.shared.b16 {%0,%1,%2,%3}, [%4];"
                 : "=r"(r[0]), "=r"(r[1]), "=r"(r[2]), "=r"(r[3]) : "r"(addr));
}
#define MMA_F16(d, a, b)                                               \
    asm volatile(                                                      \
        "mma.sync.aligned.m16n8k16.row.col.f32.f16.f16.f32 "           \
        "{%0,%1,%2,%3}, {%4,%5,%6,%7}, {%8,%9}, {%0,%1,%2,%3};\n"      \
        : "+f"((d)[0]), "+f"((d)[1]), "+f"((d)[2]), "+f"((d)[3])       \
        : "r"((a)[0]), "r"((a)[1]), "r"((a)[2]), "r"((a)[3]),          \
          "r"((b)[0]), "r"((b)[1]))

// ---------------------------------------------------------------------------
// Stage 0: transpose + convert Wenc [E,A] f32 -> g_WhT [A,E] fp16
// ---------------------------------------------------------------------------
__global__ void transpose_kernel(const float* __restrict__ W) {
    __shared__ float tile[32][33];
    const int k0 = blockIdx.x * 32, n0 = blockIdx.y * 32;
    for (int i = threadIdx.y; i < 32; i += 8)
        tile[i][threadIdx.x] = W[(size_t)(k0 + i) * A_ + n0 + threadIdx.x];
    __syncthreads();
    for (int i = threadIdx.y; i < 32; i += 8)
        g_WhT[(size_t)(n0 + i) * E_ + k0 + threadIdx.x] =
            __float2half_rn(tile[threadIdx.x][i]);
}

// ---------------------------------------------------------------------------
// Stage 1: att2[b,a] = decoder_hidden[b,:] @ W_dec[:,a] + b_dec[a]
// ---------------------------------------------------------------------------
__global__ void att2_kernel(const float* __restrict__ dh,
                            const float* __restrict__ Wdec,
                            const float* __restrict__ bdec) {
    __shared__ float sdh[16][D_];
    const int colBase = blockIdx.x * 128;
    const int bBase   = blockIdx.y * 16;
    const int t = threadIdx.x;

    for (int i = t; i < 16 * D_; i += 256) {
        int bb = i / D_, k = i % D_;
        sdh[bb][k] = dh[(bBase + bb) * D_ + k];
    }
    __syncthreads();

    const int col   = colBase + (t & 127);
    const int bhalf = t >> 7;
    float acc[8];
    #pragma unroll
    for (int i = 0; i < 8; i++) acc[i] = 0.0f;

    for (int k = 0; k < D_; k++) {
        float w = Wdec[k * A_ + col];
        #pragma unroll
        for (int i = 0; i < 8; i++)
            acc[i] = fmaf(sdh[bhalf * 8 + i][k], w, acc[i]);
    }
    float bd = bdec[col];
    #pragma unroll
    for (int i = 0; i < 8; i++)
        g_att2[(bBase + bhalf * 8 + i) * A_ + col] = acc[i] + bd;
}

// ---------------------------------------------------------------------------
// Stage 2: fp16 mma.sync GEMM + fused epilogue.
//   BM=128, BN=256, BK=64 — 1024 threads (32 warps, warp tile 32x32).
//   8 warps/SMSP to hide LDSM latency (tensor pipe was 40% active at 4/SMSP).
// ---------------------------------------------------------------------------
#define ASB 144                      // smem row stride in bytes
#define KT (E_/64)                   // 32 stages
#define SM_A0 0                      // A buf: 128*144 = 18432 B
#define SM_A1 18432
#define SM_B0 36864                  // B buf: 256*144 = 36864 B
#define SM_B1 73728
#define SM_TOTAL 110592

__global__ __launch_bounds__(1024, 1)
void main_gemm_h(const float* __restrict__ enc,
                 const float* __restrict__ benc,
                 const float* __restrict__ wfull,
                 int rowTileOff) {
    extern __shared__ __align__(128) char smem[];
    const uint32_t sb = smem_u32(smem);
    const int tid  = threadIdx.x;
    const int lane = tid & 31;
    const int warp = tid >> 5;           // 0..31
    const int mw   = warp >> 3;          // 0..3  (m block of 32)
    const int nw   = warp & 7;           // 0..7  (n block of 32)
    const int rowBase = (blockIdx.x + rowTileOff) * 128;
    const int colBase = blockIdx.y * 256;
    const int part    = blockIdx.y;

    const uint32_t aBuf[2] = { sb + SM_A0, sb + SM_A1 };
    const uint32_t bBuf[2] = { sb + SM_B0, sb + SM_B1 };

    // ldmatrix per-thread address offsets (R7 formulas, 32-row warp tiles)
    const uint32_t aOff = (uint32_t)((mw * 32 + (lane & 15)) * ASB)
                        + (uint32_t)((lane >> 4) * 16);
    const int bRow = nw * 32 + (lane & 7) + ((lane >> 4) & 1) * 8;
    const uint32_t bOff = (uint32_t)(bRow * ASB)
                        + (uint32_t)(((lane >> 3) & 1) * 16);

    // A loader: 128 rows x 8 chunks(16B fp16 = 8 floats) = 1024 chunks, 1/thr
    const int ar = tid >> 3, aq = tid & 7;
    const float* aG = enc + (size_t)(rowBase + ar) * E_ + aq * 8;
    const uint32_t aSt = (uint32_t)(ar * ASB + aq * 16);

    // B loader: 256 rows x 8 chunks = 2048 chunks, 2/thr (rows br, br+128)
    const int br = tid >> 3, bq = tid & 7;
    const __half* bG = g_WhT + (size_t)(colBase + br) * E_ + bq * 8;
    const uint32_t bSt = (uint32_t)(br * ASB + bq * 16);

    auto cvt8 = [](const float* p) -> uint4 {
        float4 f0 = *(const float4*)p;
        float4 f1 = *(const float4*)(p + 4);
        __half2 h0 = __floats2half2_rn(f0.x, f0.y);
        __half2 h1 = __floats2half2_rn(f0.z, f0.w);
        __half2 h2 = __floats2half2_rn(f1.x, f1.y);
        __half2 h3 = __floats2half2_rn(f1.z, f1.w);
        uint4 u;
        u.x = *(uint32_t*)&h0; u.y = *(uint32_t*)&h1;
        u.z = *(uint32_t*)&h2; u.w = *(uint32_t*)&h3;
        return u;
    };
    auto cpB = [&](int s, int k0) {
        cp16(bBuf[s] + bSt, bG + k0);
        cp16(bBuf[s] + bSt + (uint32_t)(128 * ASB), bG + k0 + (size_t)128 * E_);
        asm volatile("cp.async.commit_group;\n" ::: "memory");
    };

    float acc[2][4][4];
    #pragma unroll
    for (int mi = 0; mi < 2; mi++)
        #pragma unroll
        for (int nj = 0; nj < 4; nj++)
            #pragma unroll
            for (int e = 0; e < 4; e++) acc[mi][nj][e] = 0.0f;

    // prologue: stage 0
    {
        *(uint4*)(smem + SM_A0 + aSt) = cvt8(aG);
        cpB(0, 0);
    }

    for (int t = 0; t < KT; t++) {
        const int s = t & 1;
        asm volatile("cp.async.wait_group 0;\n" ::: "memory");
        __syncthreads();

        uint4 aN;
        if (t + 1 < KT) {
            cpB(s ^ 1, (t + 1) * 64);
            aN = cvt8(aG + (t + 1) * 64);
        }

        const uint32_t aB = aBuf[s], bB = bBuf[s];
        #pragma unroll
        for (int kk = 0; kk < 4; kk++) {
            uint32_t af[2][4];
            ldsm4(af[0], aB + aOff + kk * 32);
            ldsm4(af[1], aB + aOff + 16 * ASB + kk * 32);
            uint32_t bf[4][2];
            #pragma unroll
            for (int p = 0; p < 2; p++) {
                uint32_t r4[4];
                ldsm4(r4, bB + bOff + p * 16 * ASB + kk * 32);
                bf[2*p][0]   = r4[0]; bf[2*p][1]   = r4[1];
                bf[2*p+1][0] = r4[2]; bf[2*p+1][1] = r4[3];
            }
            #pragma unroll
            for (int mi = 0; mi < 2; mi++)
                #pragma unroll
                for (int nj = 0; nj < 4; nj++)
                    MMA_F16(acc[mi][nj], af[mi], bf[nj]);
        }

        if (t + 1 < KT) {
            char* dst = smem + (s ? SM_A0 : SM_A1);
            *(uint4*)(dst + aSt) = aN;
        }
    }

    // ---- fused epilogue: relu(att1 + benc + att2) . wfull, per-row sums ----
    __syncthreads();                 // reuse smem
    float* sa2 = (float*)smem;       // [2][256]: benc + att2 for 2 local batches
    float* sw  = (float*)smem + 512; // [256]
    float* red = (float*)smem + 768; // [128][9]
    const int b0 = rowBase / P_;
    const int boundary = (b0 + 1) * P_ - rowBase;   // local row where batch++

    if (tid < 512) {
        int bb = b0 + (tid >> 8); if (bb > B_ - 1) bb = B_ - 1;
        int c = tid & 255;
        sa2[tid] = benc[colBase + c] + g_att2[bb * A_ + colBase + c];
    }
    if (tid >= 512 && tid < 768) sw[tid - 512] = wfull[colBase + (tid - 512)];
    __syncthreads();

    const int c0l = nw * 32 + 2 * (lane & 3);
    #pragma unroll
    for (int mi = 0; mi < 2; mi++) {
        #pragma unroll
        for (int h = 0; h < 2; h++) {
            const int rl = mw * 32 + mi * 16 + h * 8 + (lane >> 2);
            const float* a2p = sa2 + ((rl >= boundary) ? 256 : 0);
            float s = 0.0f;
            #pragma unroll
            for (int nj = 0; nj < 4; nj++) {
                const int c = c0l + nj * 8;
                float v0 = acc[mi][nj][h * 2 + 0] + a2p[c];
                float v1 = acc[mi][nj][h * 2 + 1] + a2p[c + 1];
                s = fmaf(fmaxf(v0, 0.0f), sw[c], s);
                s = fmaf(fmaxf(v1, 0.0f), sw[c + 1], s);
            }
            s += __shfl_xor_sync(0xFFFFFFFFu, s, 1);
            s += __shfl_xor_sync(0xFFFFFFFFu, s, 2);
            if ((lane & 3) == 0) red[rl * 9 + nw] = s;
        }
    }
    __syncthreads();
    if (tid < 128) {
        float s = 0.0f;
        #pragma unroll
        for (int j = 0; j < 8; j++) s += red[tid * 9 + j];
        g_attp[part * M_ + rowBase + tid] = s;
    }
}

// ---------------------------------------------------------------------------
// Stage 3 (fused softmax + awe, R14 body + batch offset): grid (E/256, 128).
// ---------------------------------------------------------------------------
__global__ void awe_kernel(const float* __restrict__ enc,
                           float* __restrict__ alpha_out,
                           float* __restrict__ awe_out,
                           int bOff) {
    __shared__ float sred[256];
    __shared__ float sa[P_];
    const int b = blockIdx.y + bOff;
    const int t = threadIdx.x;

    // softmax over P_=196 for batch b
    float v = -CUDART_INF_F;
    if (t < P_) {
        int r = b * P_ + t;
        v = g_attp[r] + g_attp[M_ + r];
    }
    sred[t] = v;
    __syncthreads();
    for (int s = 128; s > 0; s >>= 1) {
        if (t < s) sred[t] = fmaxf(sred[t], sred[t + s]);
        __syncthreads();
    }
    const float m = sred[0];
    __syncthreads();
    float e = (t < P_) ? expf(v - m) : 0.0f;
    sred[t] = e;
    __syncthreads();
    for (int s = 128; s > 0; s >>= 1) {
        if (t < s) sred[t] += sred[t + s];
        __syncthreads();
    }
    const float inv = 1.0f / sred[0];
    __syncthreads();
    if (t < P_) {
        float a = e * inv;
        sa[t] = a;
        if (blockIdx.x == 0) alpha_out[b * P_ + t] = a;
    }
    __syncthreads();

    // awe slice: MLP-4 p-loop (196 = 49 * 4)
    const int col = blockIdx.x * 256 + t;
    const float* base = enc + (size_t)b * P_ * E_ + col;
    float acc = 0.0f;
    #pragma unroll 2
    for (int p = 0; p < P_; p += 4) {
        float x0 = base[(size_t)(p + 0) * E_];
        float x1 = base[(size_t)(p + 1) * E_];
        float x2 = base[(size_t)(p + 2) * E_];
        float x3 = base[(size_t)(p + 3) * E_];
        acc = fmaf(x0, sa[p + 0], acc);
        acc = fmaf(x1, sa[p + 1], acc);
        acc = fmaf(x2, sa[p + 2], acc);
        acc = fmaf(x3, sa[p + 3], acc);
    }
    awe_out[(size_t)b * E_ + col] = acc;
}

// ---------------------------------------------------------------------------
extern "C" void kernel_launch(void* const* d_in, const int* in_sizes, int n_in,
                              void* d_out, int out_size) {
    const float* enc   = (const float*)d_in[0];
    const float* dh    = (const float*)d_in[1];
    const float* Wenc  = (const float*)d_in[2];
    const float* benc  = (const float*)d_in[3];
    const float* Wdec  = (const float*)d_in[4];
    const float* bdec  = (const float*)d_in[5];
    const float* wfull = (const float*)d_in[6];
    // d_in[7] = b_full: softmax-invariant, dropped.

    float* awe   = (float*)d_out;
    float* alpha = (float*)d_out + (size_t)B_ * E_;

    static cudaStream_t s2 = nullptr;
    static cudaEvent_t evFork = nullptr, evJoin = nullptr;
    if (!s2) {
        cudaFuncSetAttribute(main_gemm_h,
                             cudaFuncAttributeMaxDynamicSharedMemorySize,
                             SM_TOTAL);
        cudaStreamCreateWithFlags(&s2, cudaStreamNonBlocking);
        cudaEventCreateWithFlags(&evFork, cudaEventDisableTiming);
        cudaEventCreateWithFlags(&evJoin, cudaEventDisableTiming);
    }

    transpose_kernel<<<dim3(E_ / 32, A_ / 32), dim3(32, 8)>>>(Wenc);
    att2_kernel<<<dim3(A_ / 128, B_ / 16), 256>>>(dh, Wdec, bdec);

    // GEMM half A: row tiles 0..195  (= batches 0..127 exactly)
    main_gemm_h<<<dim3(196, 2), 1024, SM_TOTAL>>>(enc, benc, wfull, 0);
    cudaEventRecord(evFork, 0);
    cudaStreamWaitEvent(s2, evFork, 0);

    // GEMM half B on main stream; awe for batches 0..127 on side stream
    // (awe CTAs fill GEMM_B's wave-quantization holes).
    main_gemm_h<<<dim3(196, 2), 1024, SM_TOTAL>>>(enc, benc, wfull, 196);
    awe_kernel<<<dim3(E_ / 256, 128), 256, 0, s2>>>(enc, alpha, awe, 0);

    // awe for batches 128..255 on main stream after GEMM_B; then join.
    awe_kernel<<<dim3(E_ / 256, 128), 256>>>(enc, alpha, awe, 128);
    cudaEventRecord(evJoin, s2);
    cudaStreamWaitEvent(0, evJoin, 0);
}